// round 1
// baseline (speedup 1.0000x reference)
#include <cuda_runtime.h>
#include <cuda_bf16.h>

// Problem constants (fixed by the reference)
#define NND   100000      // nodes
#define NED   50000       // hyperedges
#define NNZE  1280000     // incidence nnz
#define FT    128
#define HID   64
#define NCLS  32
#define NGR   256

#define GRID_P 1184       // persistent grid for row-GEMM kernels (148*8)

// ---------------- device scratch (static; no allocation allowed) -------------
__device__ float g_x   [NND * HID];
__device__ float g_x0  [NND * HID];
__device__ float g_h   [NND * HID];
__device__ float g_esum[NED * HID];
__device__ int   g_ecnt[NED];
__device__ float g_y   [NED * HID];
__device__ float g_cls [NND * NCLS];
__device__ int   g_noff[NND + 1];
__device__ int   g_goff[NGR + 1];

// ---------------- helpers ----------------------------------------------------
__device__ __forceinline__ int lower_bound_i(const int* __restrict__ a, int n, int key) {
    int lo = 0, hi = n;
    while (lo < hi) {
        int mid = (lo + hi) >> 1;
        if (a[mid] < key) lo = mid + 1; else hi = mid;
    }
    return lo;
}

// offsets for sorted v2e_src: g_noff[v] = first index with src >= v
__global__ void k_node_off(const int* __restrict__ src) {
    int v = blockIdx.x * blockDim.x + threadIdx.x;
    if (v <= NND) g_noff[v] = lower_bound_i(src, NNZE, v);
}

// offsets for sorted all_batch: g_goff[g] = first node with batch >= g
__global__ void k_graph_off(const int* __restrict__ batch) {
    int g = threadIdx.x;
    if (g <= NGR) g_goff[g] = lower_bound_i(batch, NND, g);
}

// ---------------- input layer: x = relu(X @ W_in + b_in) ---------------------
__global__ void k_in(const float* __restrict__ X,
                     const float* __restrict__ W,
                     const float* __restrict__ b) {
    __shared__ float Ws[FT * HID];
    __shared__ float bs[HID];
    __shared__ float xr[4][FT];
    const int tx = threadIdx.x, ty = threadIdx.y;
    const int t = ty * 64 + tx;
    for (int i = t; i < FT * HID; i += 256) Ws[i] = W[i];
    if (t < HID) bs[t] = b[t];
    __syncthreads();

    for (int row0 = blockIdx.x * 4; row0 < NND; row0 += gridDim.x * 4) {
        const int row = row0 + ty;
        const bool ok = row < NND;
        __syncthreads();
        if (ok) {
            xr[ty][tx]      = X[(size_t)row * FT + tx];
            xr[ty][tx + 64] = X[(size_t)row * FT + tx + 64];
        }
        __syncthreads();
        if (ok) {
            float acc = bs[tx];
            #pragma unroll 8
            for (int k = 0; k < FT; k++) acc += xr[ty][k] * Ws[k * HID + tx];
            acc = fmaxf(acc, 0.f);
            g_x [(size_t)row * HID + tx] = acc;
            g_x0[(size_t)row * HID + tx] = acc;
        }
    }
}

// ---------------- h = relu(x@W1a+b1a) @ W1b + b1b ----------------------------
__global__ void k_h(const float* __restrict__ Wa, const float* __restrict__ ba,
                    const float* __restrict__ Wb, const float* __restrict__ bb) {
    __shared__ float Was[HID * HID], Wbs[HID * HID];
    __shared__ float bas[HID], bbs[HID];
    __shared__ float xr[4][HID], tm[4][HID];
    const int tx = threadIdx.x, ty = threadIdx.y;
    const int t = ty * 64 + tx;
    for (int i = t; i < HID * HID; i += 256) { Was[i] = Wa[i]; Wbs[i] = Wb[i]; }
    if (t < HID) { bas[t] = ba[t]; bbs[t] = bb[t]; }
    __syncthreads();

    for (int row0 = blockIdx.x * 4; row0 < NND; row0 += gridDim.x * 4) {
        const int row = row0 + ty;
        const bool ok = row < NND;
        __syncthreads();
        if (ok) xr[ty][tx] = g_x[(size_t)row * HID + tx];
        __syncthreads();
        float acc = bas[tx];
        #pragma unroll 8
        for (int k = 0; k < HID; k++) acc += xr[ty][k] * Was[k * HID + tx];
        tm[ty][tx] = fmaxf(acc, 0.f);
        __syncthreads();
        float acc2 = bbs[tx];
        #pragma unroll 8
        for (int k = 0; k < HID; k++) acc2 += tm[ty][k] * Wbs[k * HID + tx];
        if (ok) g_h[(size_t)row * HID + tx] = acc2;
    }
}

// ---------------- zero edge accumulators -------------------------------------
__global__ void k_zero_e() {
    const int tot = NED * HID;
    for (int i = blockIdx.x * blockDim.x + threadIdx.x; i < tot;
         i += gridDim.x * blockDim.x) {
        g_esum[i] = 0.f;
        if (i < NED) g_ecnt[i] = 0;
    }
}

// ---------------- V->E scatter: esum[dst] += h[src]; ecnt[dst]++ --------------
__global__ void k_scatter(const int* __restrict__ src, const int* __restrict__ dst) {
    const int tot = NNZE * 16;   // 16 float4 lanes per nnz row
    for (int idx = blockIdx.x * blockDim.x + threadIdx.x; idx < tot;
         idx += gridDim.x * blockDim.x) {
        const int i = idx >> 4;
        const int q = idx & 15;
        const int s = __ldg(&src[i]);
        const int d = __ldg(&dst[i]);
        const float4 v = *reinterpret_cast<const float4*>(&g_h[(size_t)s * HID + q * 4]);
        float* p = &g_esum[(size_t)d * HID + q * 4];
        asm volatile("red.global.add.v4.f32 [%0], {%1,%2,%3,%4};"
                     :: "l"(p), "f"(v.x), "f"(v.y), "f"(v.z), "f"(v.w) : "memory");
        if (q == 0) atomicAdd(&g_ecnt[d], 1);
    }
}

// ---------------- Y = (esum / max(cnt,1)) @ W2b  (W2b = second half of W2) ----
__global__ void k_y(const float* __restrict__ W2) {
    __shared__ float Ws[HID * HID];
    __shared__ float xr[4][HID];
    const int tx = threadIdx.x, ty = threadIdx.y;
    const int t = ty * 64 + tx;
    for (int i = t; i < HID * HID; i += 256) Ws[i] = W2[HID * HID + i]; // W2b
    __syncthreads();

    for (int row0 = blockIdx.x * 4; row0 < NED; row0 += gridDim.x * 4) {
        const int row = row0 + ty;
        const bool ok = row < NED;
        __syncthreads();
        if (ok) {
            const float c = fmaxf((float)g_ecnt[row], 1.f);
            xr[ty][tx] = g_esum[(size_t)row * HID + tx] / c;
        }
        __syncthreads();
        float acc = 0.f;
        #pragma unroll 8
        for (int k = 0; k < HID; k++) acc += xr[ty][k] * Ws[k * HID + tx];
        if (ok) g_y[(size_t)row * HID + tx] = acc;
    }
}

// ---------------- combine: segment mean over sorted src + residual + W3 + relu
// Xv[v] = cnt>0 ? x[v]@W2a + b2 + mean_j Y[dst_j]  : 0
// x[v]  = relu( (0.5*Xv + 0.5*x0[v]) @ W3 + b3 )     (in-place update of g_x)
__global__ void k_combine(const float* __restrict__ W2, const float* __restrict__ b2,
                          const float* __restrict__ W3, const float* __restrict__ b3,
                          const int* __restrict__ dst) {
    __shared__ float W2as[HID * HID], W3s[HID * HID];
    __shared__ float b2s[HID], b3s[HID];
    __shared__ float xr[4][HID], us[4][HID];
    const int tx = threadIdx.x, ty = threadIdx.y;
    const int t = ty * 64 + tx;
    for (int i = t; i < HID * HID; i += 256) { W2as[i] = W2[i]; W3s[i] = W3[i]; }
    if (t < HID) { b2s[t] = b2[t]; b3s[t] = b3[t]; }
    __syncthreads();

    for (int row0 = blockIdx.x * 4; row0 < NND; row0 += gridDim.x * 4) {
        const int v = row0 + ty;
        const bool ok = v < NND;
        __syncthreads();
        int beg = 0, end = 0;
        if (ok) {
            beg = g_noff[v];
            end = g_noff[v + 1];
            xr[ty][tx] = g_x[(size_t)v * HID + tx];
        }
        __syncthreads();
        float u = 0.f;
        if (ok) {
            float z = 0.f;
            for (int j = beg; j < end; j++) {
                const int d = __ldg(&dst[j]);
                z += g_y[(size_t)d * HID + tx];
            }
            const int cnt = end - beg;
            float xv = 0.f;
            if (cnt > 0) {
                float acc = b2s[tx];
                #pragma unroll 8
                for (int k = 0; k < HID; k++) acc += xr[ty][k] * W2as[k * HID + tx];
                xv = acc + z / (float)cnt;
            }
            u = 0.5f * xv + 0.5f * g_x0[(size_t)v * HID + tx];
        }
        us[ty][tx] = u;
        __syncthreads();
        float acc2 = b3s[tx];
        #pragma unroll 8
        for (int k = 0; k < HID; k++) acc2 += us[ty][k] * W3s[k * HID + tx];
        if (ok) g_x[(size_t)v * HID + tx] = fmaxf(acc2, 0.f);
    }
}

// ---------------- classifier: cls = relu(x@Wc1+bc1) @ Wc2 + bc2 ---------------
__global__ void k_cls(const float* __restrict__ W1, const float* __restrict__ b1,
                      const float* __restrict__ W2, const float* __restrict__ b2) {
    __shared__ float W1s[HID * HID], W2s[HID * NCLS];
    __shared__ float b1s[HID], b2s[NCLS];
    __shared__ float xr[4][HID], tm[4][HID];
    const int tx = threadIdx.x, ty = threadIdx.y;
    const int t = ty * 64 + tx;
    for (int i = t; i < HID * HID; i += 256) W1s[i] = W1[i];
    for (int i = t; i < HID * NCLS; i += 256) W2s[i] = W2[i];
    if (t < HID)  b1s[t] = b1[t];
    if (t < NCLS) b2s[t] = b2[t];
    __syncthreads();

    for (int row0 = blockIdx.x * 4; row0 < NND; row0 += gridDim.x * 4) {
        const int row = row0 + ty;
        const bool ok = row < NND;
        __syncthreads();
        if (ok) xr[ty][tx] = g_x[(size_t)row * HID + tx];
        __syncthreads();
        float acc = b1s[tx];
        #pragma unroll 8
        for (int k = 0; k < HID; k++) acc += xr[ty][k] * W1s[k * HID + tx];
        tm[ty][tx] = fmaxf(acc, 0.f);
        __syncthreads();
        if (ok && tx < NCLS) {
            float acc2 = b2s[tx];
            #pragma unroll 8
            for (int k = 0; k < HID; k++) acc2 += tm[ty][k] * W2s[k * NCLS + tx];
            g_cls[(size_t)row * NCLS + tx] = acc2;
        }
    }
}

// ---------------- readout: per-graph mean over sorted all_batch ---------------
__global__ void k_readout(float* __restrict__ out) {
    __shared__ float part[8][NCLS];
    const int g = blockIdx.x;
    const int tx = threadIdx.x, ty = threadIdx.y;  // (32, 8)
    const int beg = g_goff[g], end = g_goff[g + 1];
    float s = 0.f;
    for (int j = beg + ty; j < end; j += 8)
        s += g_cls[(size_t)j * NCLS + tx];
    part[ty][tx] = s;
    __syncthreads();
    if (ty == 0) {
        float tot = 0.f;
        #pragma unroll
        for (int r = 0; r < 8; r++) tot += part[r][tx];
        const int c = end - beg;
        out[g * NCLS + tx] = tot / fmaxf((float)c, 1.f);
    }
}

// ---------------- launch ------------------------------------------------------
extern "C" void kernel_launch(void* const* d_in, const int* in_sizes, int n_in,
                              void* d_out, int out_size) {
    const float* X       = (const float*)d_in[0];
    const int*   v2e_src = (const int*)  d_in[1];
    const int*   v2e_dst = (const int*)  d_in[2];
    const int*   batch   = (const int*)  d_in[3];
    const float* W_in    = (const float*)d_in[4];
    const float* b_in    = (const float*)d_in[5];
    const float* W1a     = (const float*)d_in[6];
    const float* b1a     = (const float*)d_in[7];
    const float* W1b     = (const float*)d_in[8];
    const float* b1b     = (const float*)d_in[9];
    const float* W2      = (const float*)d_in[10];
    const float* b2      = (const float*)d_in[11];
    const float* W3      = (const float*)d_in[12];
    const float* b3      = (const float*)d_in[13];
    const float* Wc1     = (const float*)d_in[14];
    const float* bc1     = (const float*)d_in[15];
    const float* Wc2     = (const float*)d_in[16];
    const float* bc2     = (const float*)d_in[17];
    float* out = (float*)d_out;

    const dim3 gblk(64, 4);

    k_node_off<<<(NND + 1 + 255) / 256, 256>>>(v2e_src);
    k_graph_off<<<1, NGR + 1>>>(batch);
    k_in<<<GRID_P, gblk>>>(X, W_in, b_in);

    for (int layer = 0; layer < 2; layer++) {
        k_h<<<GRID_P, gblk>>>(W1a, b1a, W1b, b1b);
        k_zero_e<<<2048, 256>>>();
        k_scatter<<<4096, 256>>>(v2e_src, v2e_dst);
        k_y<<<GRID_P, gblk>>>(W2);
        k_combine<<<GRID_P, gblk>>>(W2, b2, W3, b3, v2e_dst);
    }

    k_cls<<<GRID_P, gblk>>>(Wc1, bc1, Wc2, bc2);
    k_readout<<<NGR, dim3(32, 8)>>>(out);
}

// round 2
// speedup vs baseline: 1.9315x; 1.9315x over previous
#include <cuda_runtime.h>
#include <cuda_bf16.h>

// Problem constants (fixed by the reference)
#define NND   100000      // nodes
#define NED   50000       // hyperedges
#define NNZE  1280000     // incidence nnz
#define FT    128
#define HID   64
#define NCLS  32
#define NGR   256

#define XSTR  68          // padded shared row stride (floats, multiple of 4)
#define NB_N  1563        // ceil(NND/64)
#define NB_E  782         // ceil(NED/64)

// ---------------- device scratch (static; no allocation allowed) -------------
__device__ float g_x   [NND * HID];
__device__ float g_x0  [NND * HID];
__device__ float g_h   [NND * HID];
__device__ float g_esum[NED * HID];
__device__ int   g_ecnt[NED];
__device__ float g_y   [NED * HID];
__device__ float g_cls [NND * NCLS];
__device__ int   g_noff[NND + 1];
__device__ int   g_goff[NGR + 1];

// ---------------- helpers ----------------------------------------------------
__device__ __forceinline__ int lower_bound_i(const int* __restrict__ a, int n, int key) {
    int lo = 0, hi = n;
    while (lo < hi) {
        int mid = (lo + hi) >> 1;
        if (a[mid] < key) lo = mid + 1; else hi = mid;
    }
    return lo;
}

__global__ void k_node_off(const int* __restrict__ src) {
    int v = blockIdx.x * blockDim.x + threadIdx.x;
    if (v <= NND) g_noff[v] = lower_bound_i(src, NNZE, v);
}

__global__ void k_graph_off(const int* __restrict__ batch) {
    int g = threadIdx.x;
    if (g <= NGR) g_goff[g] = lower_bound_i(batch, NND, g);
}

// 4x4 register-tiled GEMM over a 64-row tile: acc += xs[64][K] @ Ws[K][64]
template <int K>
__device__ __forceinline__ void gemm_tile(const float* __restrict__ xs,
                                          const float* __restrict__ Ws,
                                          float acc[4][4], int tx, int ty) {
    #pragma unroll 4
    for (int k = 0; k < K; k += 4) {
        float w[4][4];
        #pragma unroll
        for (int kk = 0; kk < 4; kk++)
            *reinterpret_cast<float4*>(w[kk]) =
                *reinterpret_cast<const float4*>(&Ws[(k + kk) * 64 + tx * 4]);
        #pragma unroll
        for (int r = 0; r < 4; r++) {
            float xv[4];
            *reinterpret_cast<float4*>(xv) =
                *reinterpret_cast<const float4*>(&xs[(ty * 4 + r) * XSTR + k]);
            #pragma unroll
            for (int kk = 0; kk < 4; kk++) {
                #pragma unroll
                for (int c = 0; c < 4; c++)
                    acc[r][c] = fmaf(xv[kk], w[kk][c], acc[r][c]);
            }
        }
    }
}

// load a 64-row x 64-col tile (row-major, HID stride) into padded shared
__device__ __forceinline__ void load_tile64(float* __restrict__ xs,
                                            const float* __restrict__ g,
                                            int row0, int nrows, int t) {
    #pragma unroll
    for (int i = t; i < 64 * 16; i += 256) {
        int r  = i >> 4;
        int c4 = (i & 15) * 4;
        float4 v = make_float4(0.f, 0.f, 0.f, 0.f);
        int row = row0 + r;
        if (row < nrows) v = *reinterpret_cast<const float4*>(&g[(size_t)row * 64 + c4]);
        *reinterpret_cast<float4*>(&xs[r * XSTR + c4]) = v;
    }
}

// ---------------- input layer: x = relu(X @ W_in + b_in) ---------------------
__global__ void __launch_bounds__(256) k_in(const float* __restrict__ X,
                                            const float* __restrict__ W,
                                            const float* __restrict__ b) {
    __shared__ float Ws[64 * 64];
    __shared__ float xs[64 * XSTR];
    __shared__ float bs[64];
    const int tx = threadIdx.x, ty = threadIdx.y;
    const int t = ty * 16 + tx;
    const int row0 = blockIdx.x * 64;
    if (t < 64) bs[t] = b[t];

    float acc[4][4];
    #pragma unroll
    for (int r = 0; r < 4; r++)
        #pragma unroll
        for (int c = 0; c < 4; c++) acc[r][c] = 0.f;

    // K=128 split into two 64-chunks, reusing the shared buffers
    for (int ch = 0; ch < 2; ch++) {
        __syncthreads();
        for (int i = t; i < 64 * 64; i += 256) Ws[i] = W[ch * 64 * 64 + i];
        #pragma unroll
        for (int i = t; i < 64 * 16; i += 256) {
            int r = i >> 4, c4 = (i & 15) * 4;
            float4 v = make_float4(0.f, 0.f, 0.f, 0.f);
            int row = row0 + r;
            if (row < NND) v = *reinterpret_cast<const float4*>(&X[(size_t)row * FT + ch * 64 + c4]);
            *reinterpret_cast<float4*>(&xs[r * XSTR + c4]) = v;
        }
        __syncthreads();
        gemm_tile<64>(xs, Ws, acc, tx, ty);
    }

    #pragma unroll
    for (int r = 0; r < 4; r++) {
        int row = row0 + ty * 4 + r;
        if (row < NND) {
            float4 o;
            o.x = fmaxf(acc[r][0] + bs[tx * 4 + 0], 0.f);
            o.y = fmaxf(acc[r][1] + bs[tx * 4 + 1], 0.f);
            o.z = fmaxf(acc[r][2] + bs[tx * 4 + 2], 0.f);
            o.w = fmaxf(acc[r][3] + bs[tx * 4 + 3], 0.f);
            *reinterpret_cast<float4*>(&g_x [(size_t)row * 64 + tx * 4]) = o;
            *reinterpret_cast<float4*>(&g_x0[(size_t)row * 64 + tx * 4]) = o;
        }
    }
}

// ---------------- h = relu(x@W1a+b1a) @ W1b + b1b ----------------------------
__global__ void __launch_bounds__(256) k_h(const float* __restrict__ Wa,
                                           const float* __restrict__ ba,
                                           const float* __restrict__ Wb,
                                           const float* __restrict__ bb) {
    __shared__ float Ws[64 * 64];
    __shared__ float xs[64 * XSTR];
    __shared__ float bas[64], bbs[64];
    const int tx = threadIdx.x, ty = threadIdx.y;
    const int t = ty * 16 + tx;
    const int row0 = blockIdx.x * 64;
    for (int i = t; i < 64 * 64; i += 256) Ws[i] = Wa[i];
    if (t < 64) { bas[t] = ba[t]; bbs[t] = bb[t]; }
    load_tile64(xs, g_x, row0, NND, t);
    __syncthreads();

    float acc[4][4];
    #pragma unroll
    for (int r = 0; r < 4; r++)
        #pragma unroll
        for (int c = 0; c < 4; c++) acc[r][c] = 0.f;
    gemm_tile<64>(xs, Ws, acc, tx, ty);
    __syncthreads();

    // tm = relu(acc + ba) back into xs; reload Ws with Wb
    #pragma unroll
    for (int r = 0; r < 4; r++)
        #pragma unroll
        for (int c = 0; c < 4; c++)
            xs[(ty * 4 + r) * XSTR + tx * 4 + c] = fmaxf(acc[r][c] + bas[tx * 4 + c], 0.f);
    for (int i = t; i < 64 * 64; i += 256) Ws[i] = Wb[i];
    __syncthreads();

    float acc2[4][4];
    #pragma unroll
    for (int r = 0; r < 4; r++)
        #pragma unroll
        for (int c = 0; c < 4; c++) acc2[r][c] = 0.f;
    gemm_tile<64>(xs, Ws, acc2, tx, ty);

    #pragma unroll
    for (int r = 0; r < 4; r++) {
        int row = row0 + ty * 4 + r;
        if (row < NND) {
            float4 o;
            o.x = acc2[r][0] + bbs[tx * 4 + 0];
            o.y = acc2[r][1] + bbs[tx * 4 + 1];
            o.z = acc2[r][2] + bbs[tx * 4 + 2];
            o.w = acc2[r][3] + bbs[tx * 4 + 3];
            *reinterpret_cast<float4*>(&g_h[(size_t)row * 64 + tx * 4]) = o;
        }
    }
}

// ---------------- zero edge accumulators -------------------------------------
__global__ void k_zero_e() {
    const int tot = NED * HID;
    for (int i = blockIdx.x * blockDim.x + threadIdx.x; i < tot;
         i += gridDim.x * blockDim.x) {
        g_esum[i] = 0.f;
        if (i < NED) g_ecnt[i] = 0;
    }
}

// ---------------- V->E scatter: esum[dst] += h[src]; ecnt[dst]++ --------------
__global__ void k_scatter(const int* __restrict__ src, const int* __restrict__ dst) {
    const int tot = NNZE * 16;   // 16 float4 lanes per nnz row
    for (int idx = blockIdx.x * blockDim.x + threadIdx.x; idx < tot;
         idx += gridDim.x * blockDim.x) {
        const int i = idx >> 4;
        const int q = idx & 15;
        const int s = __ldg(&src[i]);
        const int d = __ldg(&dst[i]);
        const float4 v = *reinterpret_cast<const float4*>(&g_h[(size_t)s * HID + q * 4]);
        float* p = &g_esum[(size_t)d * HID + q * 4];
        asm volatile("red.global.add.v4.f32 [%0], {%1,%2,%3,%4};"
                     :: "l"(p), "f"(v.x), "f"(v.y), "f"(v.z), "f"(v.w) : "memory");
        if (q == 0) atomicAdd(&g_ecnt[d], 1);
    }
}

// ---------------- Y = (esum / max(cnt,1)) @ W2b -------------------------------
__global__ void __launch_bounds__(256) k_y(const float* __restrict__ W2) {
    __shared__ float Ws[64 * 64];
    __shared__ float xs[64 * XSTR];
    __shared__ float cs[64];
    const int tx = threadIdx.x, ty = threadIdx.y;
    const int t = ty * 16 + tx;
    const int row0 = blockIdx.x * 64;
    for (int i = t; i < 64 * 64; i += 256) Ws[i] = W2[64 * 64 + i];   // W2b
    if (t < 64) {
        int row = row0 + t;
        int c = (row < NED) ? g_ecnt[row] : 1;
        cs[t] = fmaxf((float)c, 1.f);
    }
    load_tile64(xs, g_esum, row0, NED, t);
    __syncthreads();

    // scale rows by 1/cnt in place
    #pragma unroll
    for (int i = t; i < 64 * 16; i += 256) {
        int r = i >> 4, c4 = (i & 15) * 4;
        float inv = 1.f / cs[r];
        float4 v = *reinterpret_cast<float4*>(&xs[r * XSTR + c4]);
        v.x *= inv; v.y *= inv; v.z *= inv; v.w *= inv;
        *reinterpret_cast<float4*>(&xs[r * XSTR + c4]) = v;
    }
    __syncthreads();

    float acc[4][4];
    #pragma unroll
    for (int r = 0; r < 4; r++)
        #pragma unroll
        for (int c = 0; c < 4; c++) acc[r][c] = 0.f;
    gemm_tile<64>(xs, Ws, acc, tx, ty);

    #pragma unroll
    for (int r = 0; r < 4; r++) {
        int row = row0 + ty * 4 + r;
        if (row < NED) {
            float4 o = make_float4(acc[r][0], acc[r][1], acc[r][2], acc[r][3]);
            *reinterpret_cast<float4*>(&g_y[(size_t)row * 64 + tx * 4]) = o;
        }
    }
}

// ---------------- combine: Xv = x@W2a + b2 + mean_j Y[dst_j]; residual; W3; relu
__global__ void __launch_bounds__(256) k_combine(const float* __restrict__ W2,
                                                 const float* __restrict__ b2,
                                                 const float* __restrict__ W3,
                                                 const float* __restrict__ b3,
                                                 const int* __restrict__ dst) {
    __shared__ float Ws[64 * 64];
    __shared__ float xs[64 * XSTR];
    __shared__ float b2s[64], b3s[64];
    __shared__ int offs[65];
    const int tx = threadIdx.x, ty = threadIdx.y;
    const int t = ty * 16 + tx;
    const int row0 = blockIdx.x * 64;
    for (int i = t; i < 64 * 64; i += 256) Ws[i] = W2[i];    // W2a
    if (t < 64) { b2s[t] = b2[t]; b3s[t] = b3[t]; }
    if (t < 65) offs[t] = g_noff[min(row0 + t, NND)];
    load_tile64(xs, g_x, row0, NND, t);
    __syncthreads();

    float acc[4][4];
    #pragma unroll
    for (int r = 0; r < 4; r++)
        #pragma unroll
        for (int c = 0; c < 4; c++) acc[r][c] = 0.f;
    gemm_tile<64>(xs, Ws, acc, tx, ty);

    // gather z[r][0..3] = sum_j Y[dst_j][tx*4 .. tx*4+3]
    float z[4][4];
    #pragma unroll
    for (int r = 0; r < 4; r++)
        #pragma unroll
        for (int c = 0; c < 4; c++) z[r][c] = 0.f;
    #pragma unroll
    for (int r = 0; r < 4; r++) {
        const int lr = ty * 4 + r;
        const int v = row0 + lr;
        if (v < NND) {
            const int beg = offs[lr], end = offs[lr + 1];
            for (int j = beg; j < end; j++) {
                const int d = __ldg(&dst[j]);
                const float4 yv = *reinterpret_cast<const float4*>(&g_y[(size_t)d * 64 + tx * 4]);
                z[r][0] += yv.x; z[r][1] += yv.y; z[r][2] += yv.z; z[r][3] += yv.w;
            }
        }
    }
    __syncthreads();   // xs & Ws free

    // reload Ws with W3; compose u into xs
    for (int i = t; i < 64 * 64; i += 256) Ws[i] = W3[i];
    #pragma unroll
    for (int r = 0; r < 4; r++) {
        const int lr = ty * 4 + r;
        const int row = row0 + lr;
        const int cnt = offs[lr + 1] - offs[lr];
        const float inv = (cnt > 0) ? 1.f / (float)cnt : 0.f;
        float4 x0v = make_float4(0.f, 0.f, 0.f, 0.f);
        if (row < NND) x0v = *reinterpret_cast<const float4*>(&g_x0[(size_t)row * 64 + tx * 4]);
        float x0a[4] = {x0v.x, x0v.y, x0v.z, x0v.w};
        #pragma unroll
        for (int c = 0; c < 4; c++) {
            float xv = 0.f;
            if (cnt > 0) xv = acc[r][c] + b2s[tx * 4 + c] + z[r][c] * inv;
            xs[lr * XSTR + tx * 4 + c] = 0.5f * xv + 0.5f * x0a[c];
        }
    }
    __syncthreads();

    float acc2[4][4];
    #pragma unroll
    for (int r = 0; r < 4; r++)
        #pragma unroll
        for (int c = 0; c < 4; c++) acc2[r][c] = 0.f;
    gemm_tile<64>(xs, Ws, acc2, tx, ty);

    #pragma unroll
    for (int r = 0; r < 4; r++) {
        int row = row0 + ty * 4 + r;
        if (row < NND) {
            float4 o;
            o.x = fmaxf(acc2[r][0] + b3s[tx * 4 + 0], 0.f);
            o.y = fmaxf(acc2[r][1] + b3s[tx * 4 + 1], 0.f);
            o.z = fmaxf(acc2[r][2] + b3s[tx * 4 + 2], 0.f);
            o.w = fmaxf(acc2[r][3] + b3s[tx * 4 + 3], 0.f);
            *reinterpret_cast<float4*>(&g_x[(size_t)row * 64 + tx * 4]) = o;
        }
    }
}

// ---------------- classifier: cls = relu(x@Wc1+bc1) @ Wc2 + bc2 ---------------
__global__ void __launch_bounds__(256) k_cls(const float* __restrict__ W1,
                                             const float* __restrict__ b1,
                                             const float* __restrict__ W2,
                                             const float* __restrict__ b2) {
    __shared__ float W1s[64 * 64];
    __shared__ float W2s[64 * 32];
    __shared__ float xs[64 * XSTR];
    __shared__ float b1s[64], b2s[32];
    const int tx = threadIdx.x, ty = threadIdx.y;
    const int t = ty * 16 + tx;
    const int row0 = blockIdx.x * 64;
    for (int i = t; i < 64 * 64; i += 256) W1s[i] = W1[i];
    for (int i = t; i < 64 * 32; i += 256) W2s[i] = W2[i];
    if (t < 64) b1s[t] = b1[t];
    if (t < 32) b2s[t] = b2[t];
    load_tile64(xs, g_x, row0, NND, t);
    __syncthreads();

    float acc[4][4];
    #pragma unroll
    for (int r = 0; r < 4; r++)
        #pragma unroll
        for (int c = 0; c < 4; c++) acc[r][c] = 0.f;
    gemm_tile<64>(xs, W1s, acc, tx, ty);
    __syncthreads();
    #pragma unroll
    for (int r = 0; r < 4; r++)
        #pragma unroll
        for (int c = 0; c < 4; c++)
            xs[(ty * 4 + r) * XSTR + tx * 4 + c] = fmaxf(acc[r][c] + b1s[tx * 4 + c], 0.f);
    __syncthreads();

    // GEMM2: 64 -> 32, each thread 4 rows x 2 cols
    float acc2[4][2];
    #pragma unroll
    for (int r = 0; r < 4; r++) { acc2[r][0] = 0.f; acc2[r][1] = 0.f; }
    #pragma unroll 4
    for (int k = 0; k < 64; k += 4) {
        float w[4][2];
        #pragma unroll
        for (int kk = 0; kk < 4; kk++)
            *reinterpret_cast<float2*>(w[kk]) =
                *reinterpret_cast<const float2*>(&W2s[(k + kk) * 32 + tx * 2]);
        #pragma unroll
        for (int r = 0; r < 4; r++) {
            float xv[4];
            *reinterpret_cast<float4*>(xv) =
                *reinterpret_cast<const float4*>(&xs[(ty * 4 + r) * XSTR + k]);
            #pragma unroll
            for (int kk = 0; kk < 4; kk++) {
                acc2[r][0] = fmaf(xv[kk], w[kk][0], acc2[r][0]);
                acc2[r][1] = fmaf(xv[kk], w[kk][1], acc2[r][1]);
            }
        }
    }
    #pragma unroll
    for (int r = 0; r < 4; r++) {
        int row = row0 + ty * 4 + r;
        if (row < NND) {
            float2 o;
            o.x = acc2[r][0] + b2s[tx * 2 + 0];
            o.y = acc2[r][1] + b2s[tx * 2 + 1];
            *reinterpret_cast<float2*>(&g_cls[(size_t)row * 32 + tx * 2]) = o;
        }
    }
}

// ---------------- readout: per-graph mean over sorted all_batch ---------------
__global__ void k_readout(float* __restrict__ out) {
    __shared__ float part[8][NCLS];
    const int g = blockIdx.x;
    const int tx = threadIdx.x, ty = threadIdx.y;  // (32, 8)
    const int beg = g_goff[g], end = g_goff[g + 1];
    float s = 0.f;
    for (int j = beg + ty; j < end; j += 8)
        s += g_cls[(size_t)j * NCLS + tx];
    part[ty][tx] = s;
    __syncthreads();
    if (ty == 0) {
        float tot = 0.f;
        #pragma unroll
        for (int r = 0; r < 8; r++) tot += part[r][tx];
        const int c = end - beg;
        out[g * NCLS + tx] = tot / fmaxf((float)c, 1.f);
    }
}

// ---------------- launch ------------------------------------------------------
extern "C" void kernel_launch(void* const* d_in, const int* in_sizes, int n_in,
                              void* d_out, int out_size) {
    const float* X       = (const float*)d_in[0];
    const int*   v2e_src = (const int*)  d_in[1];
    const int*   v2e_dst = (const int*)  d_in[2];
    const int*   batch   = (const int*)  d_in[3];
    const float* W_in    = (const float*)d_in[4];
    const float* b_in    = (const float*)d_in[5];
    const float* W1a     = (const float*)d_in[6];
    const float* b1a     = (const float*)d_in[7];
    const float* W1b     = (const float*)d_in[8];
    const float* b1b     = (const float*)d_in[9];
    const float* W2      = (const float*)d_in[10];
    const float* b2      = (const float*)d_in[11];
    const float* W3      = (const float*)d_in[12];
    const float* b3      = (const float*)d_in[13];
    const float* Wc1     = (const float*)d_in[14];
    const float* bc1     = (const float*)d_in[15];
    const float* Wc2     = (const float*)d_in[16];
    const float* bc2     = (const float*)d_in[17];
    float* out = (float*)d_out;

    const dim3 blk(16, 16);

    k_node_off<<<(NND + 1 + 255) / 256, 256>>>(v2e_src);
    k_graph_off<<<1, NGR + 1>>>(batch);
    k_in<<<NB_N, blk>>>(X, W_in, b_in);

    for (int layer = 0; layer < 2; layer++) {
        k_h<<<NB_N, blk>>>(W1a, b1a, W1b, b1b);
        k_zero_e<<<2048, 256>>>();
        k_scatter<<<4096, 256>>>(v2e_src, v2e_dst);
        k_y<<<NB_E, blk>>>(W2);
        k_combine<<<NB_N, blk>>>(W2, b2, W3, b3, v2e_dst);
    }

    k_cls<<<NB_N, blk>>>(Wc1, bc1, Wc2, bc2);
    k_readout<<<NGR, dim3(32, 8)>>>(out);
}